// round 1
// baseline (speedup 1.0000x reference)
#include <cuda_runtime.h>

#define NIMG 48
#define W    512
#define OW   510            // valid output size per dim
#define STRIPE 51           // output rows per block (510 = 10 * 51)
#define TPB  128            // threads per block; 128*4 = 512 cols covered

__device__ double g_sum;

__global__ void k_zero() { g_sum = 0.0; }

// Compute 5 horizontal 3-sums for 4 consecutive output columns from 6 inputs.
// cur layout: [hx0..3, hy0..3, hxx0..3, hyy0..3, hxy0..3]
__device__ __forceinline__ void hsums(const float* __restrict__ xr,
                                      const float* __restrict__ yr,
                                      bool full, float cur[20]) {
    float4 a = *reinterpret_cast<const float4*>(xr);
    float4 b = *reinterpret_cast<const float4*>(yr);
    float x4 = 0.f, x5 = 0.f, y4 = 0.f, y5 = 0.f;
    if (full) {
        float4 a2 = *reinterpret_cast<const float4*>(xr + 4);
        float4 b2 = *reinterpret_cast<const float4*>(yr + 4);
        x4 = a2.x; x5 = a2.y; y4 = b2.x; y5 = b2.y;
    }
    float xs[6] = {a.x, a.y, a.z, a.w, x4, x5};
    float ys[6] = {b.x, b.y, b.z, b.w, y4, y5};
#pragma unroll
    for (int j = 0; j < 4; j++) {
        cur[j]      = xs[j] + xs[j+1] + xs[j+2];
        cur[4 + j]  = ys[j] + ys[j+1] + ys[j+2];
        cur[8 + j]  = xs[j]*xs[j] + xs[j+1]*xs[j+1] + xs[j+2]*xs[j+2];
        cur[12 + j] = ys[j]*ys[j] + ys[j+1]*ys[j+1] + ys[j+2]*ys[j+2];
        cur[16 + j] = xs[j]*ys[j] + xs[j+1]*ys[j+1] + xs[j+2]*ys[j+2];
    }
}

__global__ __launch_bounds__(TPB) void k_ssim(const float* __restrict__ x,
                                              const float* __restrict__ y) {
    const int img = blockIdx.z;
    const int c   = (blockIdx.x * blockDim.x + threadIdx.x) * 4;  // first output col
    const int r0  = blockIdx.y * STRIPE;
    const int r1  = min(r0 + STRIPE, OW);

    float acc = 0.f;

    if (c < OW) {
        const bool full = (c + 5) < W;   // can we load cols c..c+5?
        const float* xb = x + (size_t)img * W * W + c;
        const float* yb = y + (size_t)img * W * W + c;

        float p0[20], p1[20], cur[20];
        hsums(xb + (size_t)(r0    ) * W, yb + (size_t)(r0    ) * W, full, p0);
        hsums(xb + (size_t)(r0 + 1) * W, yb + (size_t)(r0 + 1) * W, full, p1);

        const float inv9 = 1.f / 9.f;
        const float covn = 9.f / 8.f;
        const float C1 = 0.0001f;   // (0.01*1.0)^2
        const float C2 = 0.0009f;   // (0.03*1.0)^2

        for (int r = r0; r < r1; r++) {
            hsums(xb + (size_t)(r + 2) * W, yb + (size_t)(r + 2) * W, full, cur);
#pragma unroll
            for (int j = 0; j < 4; j++) {
                float Sx  = p0[j]      + p1[j]      + cur[j];
                float Sy  = p0[4 + j]  + p1[4 + j]  + cur[4 + j];
                float Sxx = p0[8 + j]  + p1[8 + j]  + cur[8 + j];
                float Syy = p0[12 + j] + p1[12 + j] + cur[12 + j];
                float Sxy = p0[16 + j] + p1[16 + j] + cur[16 + j];

                float ux  = Sx * inv9,  uy  = Sy * inv9;
                float uxx = Sxx * inv9, uyy = Syy * inv9, uxy = Sxy * inv9;
                float vx  = covn * (uxx - ux * ux);
                float vy  = covn * (uyy - uy * uy);
                float vxy = covn * (uxy - ux * uy);

                float A1 = 2.f * ux * uy + C1;
                float A2 = 2.f * vxy + C2;
                float B1 = ux * ux + uy * uy + C1;
                float B2 = vx + vy + C2;
                float S  = __fdividef(A1 * A2, B1 * B2);
                if (c + j < OW) acc += S;
            }
#pragma unroll
            for (int t = 0; t < 20; t++) { p0[t] = p1[t]; p1[t] = cur[t]; }
        }
    }

    // Block reduction: warp shuffle, then smem across 4 warps, one atomic per block.
    __shared__ float warp_s[TPB / 32];
#pragma unroll
    for (int o = 16; o > 0; o >>= 1)
        acc += __shfl_down_sync(0xffffffff, acc, o);
    if ((threadIdx.x & 31) == 0) warp_s[threadIdx.x >> 5] = acc;
    __syncthreads();
    if (threadIdx.x == 0) {
        float s = 0.f;
#pragma unroll
        for (int w = 0; w < TPB / 32; w++) s += warp_s[w];
        atomicAdd(&g_sum, (double)s);
    }
}

__global__ void k_final(float* __restrict__ out) {
    out[0] = (float)(1.0 - g_sum / ((double)NIMG * OW * OW));
}

extern "C" void kernel_launch(void* const* d_in, const int* in_sizes, int n_in,
                              void* d_out, int out_size) {
    const float* img1 = (const float*)d_in[0];
    const float* img2 = (const float*)d_in[1];

    k_zero<<<1, 1>>>();
    dim3 grid((W / 4 + TPB - 1) / TPB, (OW + STRIPE - 1) / STRIPE, NIMG);  // (1, 10, 48)
    k_ssim<<<grid, TPB>>>(img1, img2);
    k_final<<<1, 1>>>((float*)d_out);
}

// round 2
// speedup vs baseline: 1.2623x; 1.2623x over previous
#include <cuda_runtime.h>

#define NIMG 48
#define W    512
#define OW   510
#define STRIPE 15            // output rows per block (510 = 34 * 15, divisible by 3)
#define NSTRIPE 34
#define TPB  128             // 128 threads * 4 cols = 512 columns
#define NSLOT (NSTRIPE * NIMG)

__device__ float g_part[NSLOT];

typedef unsigned long long u64;

// ---- packed fp32x2 helpers (sm_100a) -------------------------------------
__device__ __forceinline__ u64 pk2(float a, float b) {
    u64 r; asm("mov.b64 %0,{%1,%2};" : "=l"(r) : "f"(a), "f"(b)); return r;
}
__device__ __forceinline__ float2 upk2(u64 v) {
    float2 f; asm("mov.b64 {%0,%1},%2;" : "=f"(f.x), "=f"(f.y) : "l"(v)); return f;
}
__device__ __forceinline__ u64 add2(u64 a, u64 b) {
    u64 r; asm("add.rn.f32x2 %0,%1,%2;" : "=l"(r) : "l"(a), "l"(b)); return r;
}
__device__ __forceinline__ u64 mul2(u64 a, u64 b) {
    u64 r; asm("mul.rn.f32x2 %0,%1,%2;" : "=l"(r) : "l"(a), "l"(b)); return r;
}
__device__ __forceinline__ u64 fma2(u64 a, u64 b, u64 c) {
    u64 r; asm("fma.rn.f32x2 %0,%1,%2,%3;" : "=l"(r) : "l"(a), "l"(b), "l"(c)); return r;
}

// Horizontal 3-sums for 4 output cols, packed as pairs (win0,win2) / (win1,win3).
// v layout: [hx02,hx13, hy02,hy13, hxx02,hxx13, hyy02,hyy13, hxy02,hxy13]
__device__ __forceinline__ void hsums(const float* __restrict__ xr,
                                      const float* __restrict__ yr,
                                      bool full, u64 v[10]) {
    float4 a = *reinterpret_cast<const float4*>(xr);
    float4 b = *reinterpret_cast<const float4*>(yr);
    float x4 = 0.f, x5 = 0.f, y4 = 0.f, y5 = 0.f;
    if (full) {
        float4 a2 = *reinterpret_cast<const float4*>(xr + 4);
        float4 b2 = *reinterpret_cast<const float4*>(yr + 4);
        x4 = a2.x; x5 = a2.y; y4 = b2.x; y5 = b2.y;
    }
    // q[k] = (x[k], x[k+2]) ; window j = q-index j..j+2 sums give (w_j, w_{j+2})
    u64 q0 = pk2(a.x, a.z), q1 = pk2(a.y, a.w), q2 = pk2(a.z, x4), q3 = pk2(a.w, x5);
    u64 r0 = pk2(b.x, b.z), r1 = pk2(b.y, b.w), r2 = pk2(b.z, y4), r3 = pk2(b.w, y5);
    v[0] = add2(add2(q0, q1), q2);  v[1] = add2(add2(q1, q2), q3);
    v[2] = add2(add2(r0, r1), r2);  v[3] = add2(add2(r1, r2), r3);
    u64 s0 = mul2(q0, q0), s1 = mul2(q1, q1), s2 = mul2(q2, q2), s3 = mul2(q3, q3);
    v[4] = add2(add2(s0, s1), s2);  v[5] = add2(add2(s1, s2), s3);
    s0 = mul2(r0, r0); s1 = mul2(r1, r1); s2 = mul2(r2, r2); s3 = mul2(r3, r3);
    v[6] = add2(add2(s0, s1), s2);  v[7] = add2(add2(s1, s2), s3);
    s0 = mul2(q0, r0); s1 = mul2(q1, r1); s2 = mul2(q2, r2); s3 = mul2(q3, r3);
    v[8] = add2(add2(s0, s1), s2);  v[9] = add2(add2(s1, s2), s3);
}

// Rescaled SSIM (exact algebra, no /9 normalization):
//   S = (2SxSy+81C1)(18Sxy-2SxSy+72C2) / ((Sx^2+Sy^2+81C1)(9(Sxx+Syy)-Sx^2-Sy^2+72C2))
__device__ __forceinline__ float2 pairS(u64 Sx, u64 Sy, u64 Sxx, u64 Syy, u64 Sxy) {
    const u64 c2    = pk2( 2.0f,  2.0f);
    const u64 c18   = pk2(18.0f, 18.0f);
    const u64 c9    = pk2( 9.0f,  9.0f);
    const u64 cm1   = pk2(-1.0f, -1.0f);
    const u64 cm2   = pk2(-2.0f, -2.0f);
    const u64 c81C1 = pk2(0.0081f, 0.0081f);   // 81 * (0.01)^2
    const u64 c72C2 = pk2(0.0648f, 0.0648f);   // 72 * (0.03)^2
    u64 P  = mul2(Sx, Sy);
    u64 A1 = fma2(P, c2, c81C1);
    u64 Q  = mul2(Sx, Sx); Q = fma2(Sy, Sy, Q);
    u64 B1 = add2(Q, c81C1);
    u64 A2 = fma2(Sxy, c18, c72C2); A2 = fma2(P, cm2, A2);
    u64 Rq = add2(Sxx, Syy);
    u64 B2 = fma2(Rq, c9, c72C2);   B2 = fma2(Q, cm1, B2);
    float2 n = upk2(mul2(A1, A2));
    float2 d = upk2(mul2(B1, B2));
    return make_float2(__fdividef(n.x, d.x), __fdividef(n.y, d.y));
}

__device__ __forceinline__ float ssim4(const u64* A, const u64* B, const u64* C,
                                       float m0, float m1, float m2, float m3) {
    u64 Sx02  = add2(add2(A[0], B[0]), C[0]);
    u64 Sx13  = add2(add2(A[1], B[1]), C[1]);
    u64 Sy02  = add2(add2(A[2], B[2]), C[2]);
    u64 Sy13  = add2(add2(A[3], B[3]), C[3]);
    u64 Sxx02 = add2(add2(A[4], B[4]), C[4]);
    u64 Sxx13 = add2(add2(A[5], B[5]), C[5]);
    u64 Syy02 = add2(add2(A[6], B[6]), C[6]);
    u64 Syy13 = add2(add2(A[7], B[7]), C[7]);
    u64 Sxy02 = add2(add2(A[8], B[8]), C[8]);
    u64 Sxy13 = add2(add2(A[9], B[9]), C[9]);
    float2 p02 = pairS(Sx02, Sy02, Sxx02, Syy02, Sxy02);
    float2 p13 = pairS(Sx13, Sy13, Sxx13, Syy13, Sxy13);
    float s = p02.x * m0;
    s = fmaf(p13.x, m1, s);
    s = fmaf(p02.y, m2, s);
    s = fmaf(p13.y, m3, s);
    return s;
}

__global__ __launch_bounds__(TPB) void k_ssim(const float* __restrict__ x,
                                              const float* __restrict__ y) {
    const int img = blockIdx.y;
    const int c   = threadIdx.x * 4;          // first output col of this thread
    const int r0  = blockIdx.x * STRIPE;

    const bool full = (c + 5) < W;
    const float m0 = (c + 0 < OW) ? 1.f : 0.f;
    const float m1 = (c + 1 < OW) ? 1.f : 0.f;
    const float m2 = (c + 2 < OW) ? 1.f : 0.f;
    const float m3 = (c + 3 < OW) ? 1.f : 0.f;

    const float* xb = x + (size_t)img * W * W + c;
    const float* yb = y + (size_t)img * W * W + c;

    u64 R0[10], R1[10], R2[10];
    hsums(xb + (size_t)r0 * W,       yb + (size_t)r0 * W,       full, R0);
    hsums(xb + (size_t)(r0 + 1) * W, yb + (size_t)(r0 + 1) * W, full, R1);

    const float* xr = xb + (size_t)(r0 + 2) * W;
    const float* yr = yb + (size_t)(r0 + 2) * W;

    float acc = 0.f;
#pragma unroll 1
    for (int i = 0; i < STRIPE / 3; i++) {
        hsums(xr, yr, full, R2); xr += W; yr += W;
        acc += ssim4(R0, R1, R2, m0, m1, m2, m3);
        hsums(xr, yr, full, R0); xr += W; yr += W;
        acc += ssim4(R1, R2, R0, m0, m1, m2, m3);
        hsums(xr, yr, full, R1); xr += W; yr += W;
        acc += ssim4(R2, R0, R1, m0, m1, m2, m3);
    }

    // Block reduction -> per-block slot (no zeroing needed: every slot written)
    __shared__ float warp_s[TPB / 32];
#pragma unroll
    for (int o = 16; o > 0; o >>= 1)
        acc += __shfl_down_sync(0xffffffff, acc, o);
    if ((threadIdx.x & 31) == 0) warp_s[threadIdx.x >> 5] = acc;
    __syncthreads();
    if (threadIdx.x == 0) {
        float s = 0.f;
#pragma unroll
        for (int w = 0; w < TPB / 32; w++) s += warp_s[w];
        g_part[blockIdx.x + NSTRIPE * blockIdx.y] = s;
    }
}

__global__ __launch_bounds__(256) void k_final(float* __restrict__ out) {
    __shared__ double warp_s[8];
    double s = 0.0;
    for (int i = threadIdx.x; i < NSLOT; i += 256) s += (double)g_part[i];
#pragma unroll
    for (int o = 16; o > 0; o >>= 1)
        s += __shfl_down_sync(0xffffffff, s, o);
    if ((threadIdx.x & 31) == 0) warp_s[threadIdx.x >> 5] = s;
    __syncthreads();
    if (threadIdx.x == 0) {
        double t = 0.0;
#pragma unroll
        for (int w = 0; w < 8; w++) t += warp_s[w];
        out[0] = (float)(1.0 - t / ((double)NIMG * OW * OW));
    }
}

extern "C" void kernel_launch(void* const* d_in, const int* in_sizes, int n_in,
                              void* d_out, int out_size) {
    const float* img1 = (const float*)d_in[0];
    const float* img2 = (const float*)d_in[1];

    dim3 grid(NSTRIPE, NIMG);   // 34 * 48 = 1632 blocks
    k_ssim<<<grid, TPB>>>(img1, img2);
    k_final<<<1, 256>>>((float*)d_out);
}